// round 13
// baseline (speedup 1.0000x reference)
#include <cuda_runtime.h>
#include <math.h>

// RBFSolver: out[0,f,t] = sum_k w_k / (1 + 4pi^2 ex^2)
//            out[1,f,t] = -2pi sum_k w_k ex / (1 + 4pi^2 ex^2)
// ex = exp(log f + log t + y_k), y = linspace(-50,50,500), w_k = exp(-y_k^2)*dy.
//
// The reference's Riemann sum equals int e^{-y^2} g(s+y) dy to ~1e-21; g is
// analytic in |Im y| < pi/2, so 8-point GAUSS-HERMITE reproduces it to
// ~8e-5 relative (measured R9-R12) vs tolerance 1e-3. 500 grid points ->
// 8 GH points; 4 outputs per thread in two packed f32x2 streams.
//
// Session findings baked in:
//  * no log: exp(log f + log t) = f * exp(log t);
//  * -2pi folded into esc (denominator is sign-blind -> im accumulator IS
//    a_im, epilogue is two STG.128 of the raw accumulators);
//  * GH table host-computed (double), passed by value, compile-time-indexed
//    only (uniform const reads; divergent LDC serializes — R5);
//  * batched reciprocal: 1 MUFU.RCP per packed lane-pair per point;
//  * single launch: kernel sits on a hard ~4.3us launch floor (R9-R12
//    sweep: 4x threads, 8x CTAs, 3.5x instrs -> no change), so structure
//    minimizes total issued work and epilogue size.
// R13: 256 CTAs x 128 threads (was 128x256): ~16 warps on active SMs to
// cover the per-warp dependent chain during the short execution window.

#define GH_N    8
#define F_DIM   512
#define T_DIM   256
#define BLK     128
#define NBLK    (F_DIM * T_DIM / 4 / BLK)   // 256

typedef unsigned long long u64;

#define MUL2(o,a,b)   asm("mul.rn.f32x2 %0, %1, %2;"     : "=l"(o) : "l"(a), "l"(b))
#define ADD2(o,a,b)   asm("add.rn.f32x2 %0, %1, %2;"     : "=l"(o) : "l"(a), "l"(b))
#define FMA2(o,a,b,c) asm("fma.rn.f32x2 %0, %1, %2, %3;" : "=l"(o) : "l"(a), "l"(b), "l"(c))
#define PACK2(o,lo,hi)   asm("mov.b64 %0, {%1, %2};" : "=l"(o) : "f"(lo), "f"(hi))
#define UNPACK2(lo,hi,i) asm("mov.b64 {%0, %1}, %2;" : "=f"(lo), "=f"(hi) : "l"(i))
#define RCPA(o,a)     asm("rcp.approx.ftz.f32 %0, %1;" : "=f"(o) : "f"(a))

struct QuadTbl {
    float2 p[GH_N];     // (E_i = exp(node_i), w_i)
};

__global__ __launch_bounds__(BLK)
void rbf_solver_kernel(const float* __restrict__ f_vec,
                       const float* __restrict__ log_t_vec,
                       float* __restrict__ out,
                       const QuadTbl tbl)
{
    const int gid = blockIdx.x * BLK + threadIdx.x;   // 0..32767
    const int f   = gid >> 6;            // 0..511, uniform per warp
    const int tq  = gid & 63;            // t-quad index; t = 4*tq .. 4*tq+3

    // esc = -2pi * f * exp(log t); d = fma(exF,exF,1) is sign-invariant,
    // so the im accumulator comes out as a_im directly.
    const float  c  = -6.283185307179586f * f_vec[f];
    const float4 lt = ((const float4*)log_t_vec)[tq];     // LDG.128
    const float  e0 = c * __expf(lt.x);
    const float  e1 = c * __expf(lt.y);
    const float  e2 = c * __expf(lt.z);
    const float  e3 = c * __expf(lt.w);

    u64 escA, escB, one2, reA, reB, imA, imB;
    PACK2(escA, e0, e1);
    PACK2(escB, e2, e3);
    {
        float one = 1.0f, zero = 0.0f;
        PACK2(one2, one, one);
        PACK2(reA, zero, zero);  PACK2(reB, zero, zero);
        PACK2(imA, zero, zero);  PACK2(imB, zero, zero);
    }

    #pragma unroll
    for (int i = 0; i < GH_N; ++i) {
        float2 v = tbl.p[i];                 // uniform const-bank read
        u64 E2, w2;
        PACK2(E2, v.x, v.x);
        PACK2(w2, v.y, v.y);

        // Stream A (t lanes 0,1) and stream B (t lanes 2,3): independent.
        u64 exFA;  MUL2(exFA, escA, E2);
        u64 exFB;  MUL2(exFB, escB, E2);
        u64 dA;    FMA2(dA, exFA, exFA, one2);
        u64 dB;    FMA2(dB, exFB, exFB, one2);

        float a0, a1, b0, b1;
        UNPACK2(a0, a1, dA);
        UNPACK2(b0, b1, dB);
        float pA = a0 * a1;                 // <= ~2e15, rcp-safe
        float pB = b0 * b1;
        float rA; RCPA(rA, pA);             // MUFU.RCP
        float rB; RCPA(rB, pB);             // MUFU.RCP
        u64 r2A;   PACK2(r2A, rA * a1, rA * a0);
        u64 r2B;   PACK2(r2B, rB * b1, rB * b0);

        u64 twA;   MUL2(twA, w2, r2A);
        u64 twB;   MUL2(twB, w2, r2B);
        ADD2(reA, reA, twA);
        ADD2(reB, reB, twB);
        FMA2(imA, twA, exFA, imA);
        FMA2(imB, twB, exFB, imB);
    }

    // 4 contiguous outputs per channel -> one STG.128 each.
    ulonglong2* o128 = (ulonglong2*)out;
    o128[gid]                       = make_ulonglong2(reA, reB);  // a_re
    o128[(F_DIM * T_DIM / 4) + gid] = make_ulonglong2(imA, imB);  // a_im
}

// ---------------------------------------------------------------------------
// Host: 8-point Gauss-Hermite nodes/weights (physicists' H_8), computed in
// double via sign-scan + bisection. Input-independent; runs at capture time.
// ---------------------------------------------------------------------------
static double hermite_H(int n, double x)
{
    double h0 = 1.0, h1 = 2.0 * x;
    for (int k = 1; k < n; ++k) {
        double h2 = 2.0 * x * h1 - 2.0 * (double)k * h0;
        h0 = h1; h1 = h2;
    }
    return h1;
}

extern "C" void kernel_launch(void* const* d_in, const int* in_sizes, int n_in,
                              void* d_out, int out_size)
{
    const float* f_vec     = (const float*)d_in[0];   // (512,)
    const float* log_t_vec = (const float*)d_in[1];   // (256,)
    float* out             = (float*)d_out;           // (2, 512, 256)

    (void)in_sizes; (void)n_in; (void)out_size;

    // Positive roots of H_8 by scan + bisection on (0, 4).
    double xr[GH_N];      // all 8 nodes, ascending
    double wt[GH_N];
    {
        double roots[GH_N / 2];
        int nr = 0;
        double step = 1e-3;
        double prev = hermite_H(GH_N, 1e-12);
        for (double x = step; x < 4.0 && nr < GH_N / 2; x += step) {
            double cur = hermite_H(GH_N, x);
            if (prev * cur < 0.0) {
                double lo = x - step, hi = x;
                for (int it = 0; it < 80; ++it) {
                    double mid = 0.5 * (lo + hi);
                    double fm = hermite_H(GH_N, mid);
                    if (fm * prev <= 0.0) hi = mid; else lo = mid;
                }
                roots[nr++] = 0.5 * (lo + hi);
            }
            prev = cur;
        }
        // weights: w_i = 2^{n-1} n! sqrt(pi) / (n^2 * H_{n-1}(x_i)^2)
        double fact = 1.0;
        for (int k = 2; k <= GH_N; ++k) fact *= (double)k;
        const double wnum = ldexp(1.0, GH_N - 1) * fact * sqrt(3.14159265358979323846)
                            / ((double)GH_N * (double)GH_N);
        for (int i = 0; i < GH_N / 2; ++i) {
            double hm = hermite_H(GH_N - 1, roots[i]);
            double w  = wnum / (hm * hm);
            xr[GH_N / 2 + i]     =  roots[i];
            xr[GH_N / 2 - 1 - i] = -roots[i];
            wt[GH_N / 2 + i]     = w;
            wt[GH_N / 2 - 1 - i] = w;
        }
    }

    QuadTbl tbl;
    for (int i = 0; i < GH_N; ++i)
        tbl.p[i] = make_float2((float)exp(xr[i]), (float)wt[i]);

    rbf_solver_kernel<<<NBLK, BLK>>>(f_vec, log_t_vec, out, tbl);
}

// round 14
// speedup vs baseline: 1.0693x; 1.0693x over previous
#include <cuda_runtime.h>
#include <math.h>

// RBFSolver: out[0,f,t] = sum_k w_k / (1 + 4pi^2 ex^2)
//            out[1,f,t] = -2pi sum_k w_k ex / (1 + 4pi^2 ex^2)
// ex = exp(log f + log t + y_k), y = linspace(-50,50,500), w_k = exp(-y_k^2)*dy.
//
// The reference's Riemann sum equals int e^{-y^2} g(s+y) dy to ~1e-21; g is
// analytic in |Im y| < pi/2, so 8-point GAUSS-HERMITE reproduces it to
// ~8e-5 relative (measured R9-R13) vs tolerance 1e-3.
//
// FINAL (R11 configuration, best measured dur of the minimal-kernel family):
// two outputs (t-pair) per f32x2 lane, loop over 8 GH points:
//  * no log: exp(log f + log t) = f * exp(log t);
//  * -2pi folded into esc (denominator is sign-blind -> im accumulator IS
//    a_im); packed accumulators ARE the output pairs -> two STG.64;
//  * GH table host-computed (double), passed by value, compile-time-indexed
//    only (uniform const reads; divergent LDC serializes — R5);
//  * batched reciprocal: 1 MUFU.RCP per point across the two t-lanes;
//  * single launch; 1024 CTAs (balance, R10).
// Session conclusion: kernel sits on a hard ~4.3us launch floor (R9-R13:
// 4x threads / 8x CTAs / 3.5x instrs -> no kernel-time change); compute is
// ~0.9us of it. This variant is floor-optimal.

#define GH_N    8
#define F_DIM   512
#define T_DIM   256
#define BLK     64
#define NBLK    (F_DIM * T_DIM / 2 / BLK)   // 1024

typedef unsigned long long u64;

#define MUL2(o,a,b)   asm("mul.rn.f32x2 %0, %1, %2;"     : "=l"(o) : "l"(a), "l"(b))
#define ADD2(o,a,b)   asm("add.rn.f32x2 %0, %1, %2;"     : "=l"(o) : "l"(a), "l"(b))
#define FMA2(o,a,b,c) asm("fma.rn.f32x2 %0, %1, %2, %3;" : "=l"(o) : "l"(a), "l"(b), "l"(c))
#define PACK2(o,lo,hi)   asm("mov.b64 %0, {%1, %2};" : "=l"(o) : "f"(lo), "f"(hi))
#define UNPACK2(lo,hi,i) asm("mov.b64 {%0, %1}, %2;" : "=f"(lo), "=f"(hi) : "l"(i))
#define RCPA(o,a)     asm("rcp.approx.ftz.f32 %0, %1;" : "=f"(o) : "f"(a))

struct QuadTbl {
    float2 p[GH_N];     // (E_i = exp(node_i), w_i)
};

__global__ __launch_bounds__(BLK)
void rbf_solver_kernel(const float* __restrict__ f_vec,
                       const float* __restrict__ log_t_vec,
                       float* __restrict__ out,
                       const QuadTbl tbl)
{
    const int gid = blockIdx.x * BLK + threadIdx.x;   // 0..65535
    const int f   = gid >> 7;            // 0..511, uniform per block
    const int tp  = gid & 127;           // t-pair index; t = 2*tp, 2*tp+1

    // esc = -2pi * f * exp(log t)  (the -2pi rides along; d is sign-blind,
    // so the im accumulation comes out as a_im directly)
    const float  c  = -6.283185307179586f * f_vec[f];
    const float2 lt = ((const float2*)log_t_vec)[tp];     // LDG.64
    const float  e0 = c * __expf(lt.x);
    const float  e1 = c * __expf(lt.y);

    u64 esc2, one2, re2, im2;
    PACK2(esc2, e0, e1);
    {
        float one = 1.0f, zero = 0.0f;
        PACK2(one2, one, one);
        PACK2(re2, zero, zero);
        PACK2(im2, zero, zero);
    }

    #pragma unroll
    for (int i = 0; i < GH_N; ++i) {
        float2 v = tbl.p[i];                 // uniform const-bank read
        u64 E2, w2;
        PACK2(E2, v.x, v.x);
        PACK2(w2, v.y, v.y);

        u64 exF2;  MUL2(exF2, esc2, E2);            // -2pi*ex, per t-lane
        u64 d2;    FMA2(d2, exF2, exF2, one2);      // 1 + (2pi ex)^2

        // Batched reciprocal across the two t-lanes: one MUFU per point.
        float dlo, dhi;  UNPACK2(dlo, dhi, d2);
        float pr = dlo * dhi;                       // <= ~2e15, safe
        float rr; RCPA(rr, pr);                     // MUFU.RCP (x1)
        float rlo = rr * dhi;
        float rhi = rr * dlo;
        u64 r2;    PACK2(r2, rlo, rhi);

        u64 tw2;   MUL2(tw2, w2, r2);               // w / denom
        ADD2(re2, re2, tw2);                        // -> (a_re_t0, a_re_t1)
        FMA2(im2, tw2, exF2, im2);                  // -> (a_im_t0, a_im_t1)
    }

    // Packed accumulators are the output pairs: direct 64-bit stores.
    u64* o64 = (u64*)out;
    const int idx = gid;                     // (f*256 + 2*tp)/2 == gid
    o64[idx]                         = re2;  // a_re[f, 2tp..2tp+1]
    o64[(F_DIM * T_DIM / 2) + idx]   = im2;  // a_im[f, 2tp..2tp+1]
}

// ---------------------------------------------------------------------------
// Host: 8-point Gauss-Hermite nodes/weights (physicists' H_8), computed in
// double via sign-scan + bisection. Input-independent; runs at capture time.
// ---------------------------------------------------------------------------
static double hermite_H(int n, double x)
{
    double h0 = 1.0, h1 = 2.0 * x;
    for (int k = 1; k < n; ++k) {
        double h2 = 2.0 * x * h1 - 2.0 * (double)k * h0;
        h0 = h1; h1 = h2;
    }
    return h1;
}

extern "C" void kernel_launch(void* const* d_in, const int* in_sizes, int n_in,
                              void* d_out, int out_size)
{
    const float* f_vec     = (const float*)d_in[0];   // (512,)
    const float* log_t_vec = (const float*)d_in[1];   // (256,)
    float* out             = (float*)d_out;           // (2, 512, 256)

    (void)in_sizes; (void)n_in; (void)out_size;

    // Positive roots of H_8 by scan + bisection on (0, 4).
    double xr[GH_N];      // all 8 nodes, ascending
    double wt[GH_N];
    {
        double roots[GH_N / 2];
        int nr = 0;
        double step = 1e-3;
        double prev = hermite_H(GH_N, 1e-12);
        for (double x = step; x < 4.0 && nr < GH_N / 2; x += step) {
            double cur = hermite_H(GH_N, x);
            if (prev * cur < 0.0) {
                double lo = x - step, hi = x;
                for (int it = 0; it < 80; ++it) {
                    double mid = 0.5 * (lo + hi);
                    double fm = hermite_H(GH_N, mid);
                    if (fm * prev <= 0.0) hi = mid; else lo = mid;
                }
                roots[nr++] = 0.5 * (lo + hi);
            }
            prev = cur;
        }
        // weights: w_i = 2^{n-1} n! sqrt(pi) / (n^2 * H_{n-1}(x_i)^2)
        double fact = 1.0;
        for (int k = 2; k <= GH_N; ++k) fact *= (double)k;
        const double wnum = ldexp(1.0, GH_N - 1) * fact * sqrt(3.14159265358979323846)
                            / ((double)GH_N * (double)GH_N);
        for (int i = 0; i < GH_N / 2; ++i) {
            double hm = hermite_H(GH_N - 1, roots[i]);
            double w  = wnum / (hm * hm);
            xr[GH_N / 2 + i]     =  roots[i];
            xr[GH_N / 2 - 1 - i] = -roots[i];
            wt[GH_N / 2 + i]     = w;
            wt[GH_N / 2 - 1 - i] = w;
        }
    }

    QuadTbl tbl;
    for (int i = 0; i < GH_N; ++i)
        tbl.p[i] = make_float2((float)exp(xr[i]), (float)wt[i]);

    rbf_solver_kernel<<<NBLK, BLK>>>(f_vec, log_t_vec, out, tbl);
}